// round 14
// baseline (speedup 1.0000x reference)
#include <cuda_runtime.h>
#include <cuda_bf16.h>
#include <cstdint>
#include <cstddef>

// Problem constants
#define N_TOK 4096
#define DIM   3584
#define HID   28672
#define TOPK  32
#define RANK  48      // candidate rank target (margin 16 ranks ~ 9 sigma for int8 encode)
#define CAP   96      // candidate capacity per token

// ---------------- scratch (device globals) ----------------
__device__ int8_t g_x8[(size_t)N_TOK * DIM];          // x quantized int8 (per-row scale)
__device__ int8_t g_w8[(size_t)HID * DIM];            // W_enc quantized int8 (per-row scale)
__device__ float  g_sx[N_TOK];                        // x row scales
__device__ float  g_sw[HID];                          // W row scales
__device__ __nv_bfloat16 g_Zb[(size_t)N_TOK * HID];   // approx z (relu'd) in bf16
__device__ float g_WdT[(size_t)HID * DIM];            // W_dec transposed [H, D]
__device__ int   g_cand[(size_t)N_TOK * CAP];
__device__ int   g_ccnt[N_TOK];
__device__ int   g_tki[N_TOK * TOPK];
__device__ float g_tkv[N_TOK * TOPK];
__device__ float g_rp[N_TOK];
__device__ float g_sp[N_TOK];

// ---------------- small PTX helpers (baseline sm_80+ features) ----------------
__device__ __forceinline__ uint32_t smem_u32(const void* p) {
    uint32_t a;
    asm("{ .reg .u64 t; cvta.to.shared.u64 t, %1; cvt.u32.u64 %0, t; }" : "=r"(a) : "l"(p));
    return a;
}
__device__ __forceinline__ void cp_async16(uint32_t smaddr, const void* g) {
    asm volatile("cp.async.cg.shared.global [%0], [%1], 16;" :: "r"(smaddr), "l"(g) : "memory");
}
__device__ __forceinline__ void cp_commit() {
    asm volatile("cp.async.commit_group;" ::: "memory");
}
__device__ __forceinline__ void cp_wait2() {
    asm volatile("cp.async.wait_group 2;" ::: "memory");
}
__device__ __forceinline__ void ldsm4(uint32_t* r, uint32_t addr) {
    asm volatile("ldmatrix.sync.aligned.m8n8.x4.shared.b16 {%0,%1,%2,%3}, [%4];"
                 : "=r"(r[0]), "=r"(r[1]), "=r"(r[2]), "=r"(r[3]) : "r"(addr));
}
// int8 IMMA: m16n8k32, s32 accumulate (native single instruction since Turing)
__device__ __forceinline__ void mma16832s8(int* c, const uint32_t* a, uint32_t b0, uint32_t b1) {
    asm volatile("mma.sync.aligned.m16n8k32.row.col.s32.s8.s8.s32 "
                 "{%0,%1,%2,%3},{%4,%5,%6,%7},{%8,%9},{%0,%1,%2,%3};"
                 : "+r"(c[0]), "+r"(c[1]), "+r"(c[2]), "+r"(c[3])
                 : "r"(a[0]), "r"(a[1]), "r"(a[2]), "r"(a[3]), "r"(b0), "r"(b1));
}

// ---------------- per-row symmetric int8 quantization ----------------
// One CTA (256 threads) per row of `ncols` fp32. scale = max|row|/127.
__global__ __launch_bounds__(256)
void quant_rows_kernel(const float* __restrict__ src, int8_t* __restrict__ dst,
                       float* __restrict__ scales, int ncols)
{
    __shared__ float srow[DIM];
    __shared__ float smax[8];
    const int r = blockIdx.x, tid = threadIdx.x, lane = tid & 31, wid = tid >> 5;
    const float4* in4 = (const float4*)(src + (size_t)r * ncols);

    float mx = 0.0f;
    for (int i = tid; i < ncols / 4; i += 256) {
        float4 v = in4[i];
        ((float4*)srow)[i] = v;
        mx = fmaxf(mx, fmaxf(fmaxf(fabsf(v.x), fabsf(v.y)), fmaxf(fabsf(v.z), fabsf(v.w))));
    }
#pragma unroll
    for (int o = 16; o; o >>= 1) mx = fmaxf(mx, __shfl_down_sync(0xffffffffu, mx, o));
    if (lane == 0) smax[wid] = mx;
    __syncthreads();
    if (tid == 0) {
        float m = smax[0];
#pragma unroll
        for (int i = 1; i < 8; i++) m = fmaxf(m, smax[i]);
        smax[0] = fmaxf(m, 1e-30f);
        scales[r] = smax[0] * (1.0f / 127.0f);
    }
    __syncthreads();
    const float q = 127.0f / smax[0];

    uint32_t* out = (uint32_t*)(dst + (size_t)r * ncols);
    for (int i = tid; i < ncols / 4; i += 256) {
        float4 v = ((const float4*)srow)[i];
        int b0 = __float2int_rn(v.x * q), b1 = __float2int_rn(v.y * q);
        int b2 = __float2int_rn(v.z * q), b3 = __float2int_rn(v.w * q);
        out[i] = (uint32_t)(b0 & 0xff) | ((uint32_t)(b1 & 0xff) << 8)
               | ((uint32_t)(b2 & 0xff) << 16) | ((uint32_t)(b3 & 0xff) << 24);
    }
}

// ============================================================================
// Encode GEMM (int8 IMMA m16n8k32): Zb = relu(acc * sx[m]*sw[h] + b_enc), bf16
// Same smem geometry / fragment maps as the validated fp8 k32 kernel (R12).
// BM=BN=128, BK=64 bytes, 4-stage cp.async pipeline, 8 warps 2x4, 2 CTAs/SM.
// NIT = 56 (half the bf16 kernel's 112) at native IMMA rate.
// ============================================================================
#define GM_BK      64                    // int8 elements (= 64 bytes) per iter
#define GM_STAGES  4
#define ROW_BYTES  80                    // 64B data + 16B pad
#define STAGE_B    (128 * ROW_BYTES)     // per-matrix stage: 10240 B
#define GEMM_SMEM  (GM_STAGES * 2 * STAGE_B)   // 81920 B

__global__ __launch_bounds__(256, 2)
void encode_mma_kernel(const int8_t* __restrict__ A8,   // [N_TOK][DIM] int8
                       const int8_t* __restrict__ B8,   // [HID][DIM] int8
                       const float* __restrict__ sx,    // [N_TOK]
                       const float* __restrict__ sw,    // [HID]
                       const float* __restrict__ bias,
                       __nv_bfloat16* __restrict__ Zb)  // [N_TOK][HID]
{
    extern __shared__ char sm[];
    const uint32_t smb = smem_u32(sm);
    const int tid = threadIdx.x, lane = tid & 31, wid = tid >> 5;

    // panel remap: 256 CTAs/panel = 32 M-tiles x 8 N-tiles (keeps B in L2 per wave)
    const int L = blockIdx.x;
    const int panel = L >> 8, within = L & 255;
    const int m0 = (within & 31) * 128;
    const int n0 = (panel * 8 + (within >> 5)) * 128;

    const int wm = (wid >> 2) * 64;      // warp M offset (0/64)
    const int wn = (wid & 3) * 32;       // warp N offset (0..96)

    // per stage per matrix: 128 rows x 64B = 4 chunks(16B)/row = 512 chunks
    auto load_stage = [&](int it, int s) {
        const uint32_t sa = smb + (uint32_t)s * (2 * STAGE_B);
        const uint32_t sb = sa + STAGE_B;
#pragma unroll
        for (int u = 0; u < 2; u++) {
            int g = tid + u * 256;
            int row = g >> 2, ch = g & 3;
            cp_async16(sa + row * ROW_BYTES + ch * 16,
                       A8 + (size_t)(m0 + row) * DIM + it * GM_BK + ch * 16);
            cp_async16(sb + row * ROW_BYTES + ch * 16,
                       B8 + (size_t)(n0 + row) * DIM + it * GM_BK + ch * 16);
        }
    };

    const int NIT = DIM / GM_BK;   // 56
    for (int s = 0; s < 3; s++) { load_stage(s, s); cp_commit(); }

    int acc[4][4][4];
#pragma unroll
    for (int i = 0; i < 4; i++)
#pragma unroll
        for (int j = 0; j < 4; j++)
#pragma unroll
            for (int k = 0; k < 4; k++) acc[i][j][k] = 0;

    const int a_row  = wm + (lane & 15);
    const int a_kb   = (lane >> 4) * 16;
    const int b_row  = wn + ((lane >> 4) & 1) * 8 + (lane & 7);
    const int b_kb   = ((lane >> 3) & 1) * 16;

    for (int i = 0; i < NIT; i++) {
        cp_wait2();
        __syncthreads();
        const int s = i & 3;
        const uint32_t sa = smb + (uint32_t)s * (2 * STAGE_B);
        const uint32_t sb = sa + STAGE_B;

        uint32_t a[4][4], b[2][4];
        // ---- k-half 0 (bytes 0..31) ----
#pragma unroll
        for (int mt = 0; mt < 4; mt++)
            ldsm4(a[mt], sa + (a_row + mt * 16) * ROW_BYTES + a_kb);
#pragma unroll
        for (int p = 0; p < 2; p++)
            ldsm4(b[p], sb + (b_row + p * 16) * ROW_BYTES + b_kb);

        if (i + 3 < NIT) load_stage(i + 3, (i + 3) & 3);
        cp_commit();

#pragma unroll
        for (int mt = 0; mt < 4; mt++)
#pragma unroll
            for (int nt = 0; nt < 4; nt++)
                mma16832s8(acc[mt][nt], a[mt],
                           b[nt >> 1][(nt & 1) * 2], b[nt >> 1][(nt & 1) * 2 + 1]);

        // ---- k-half 1 (bytes 32..63) ----
#pragma unroll
        for (int mt = 0; mt < 4; mt++)
            ldsm4(a[mt], sa + (a_row + mt * 16) * ROW_BYTES + 32 + a_kb);
#pragma unroll
        for (int p = 0; p < 2; p++)
            ldsm4(b[p], sb + (b_row + p * 16) * ROW_BYTES + 32 + b_kb);

#pragma unroll
        for (int mt = 0; mt < 4; mt++)
#pragma unroll
            for (int nt = 0; nt < 4; nt++)
                mma16832s8(acc[mt][nt], a[mt],
                           b[nt >> 1][(nt & 1) * 2], b[nt >> 1][(nt & 1) * 2 + 1]);
    }

    // epilogue: scale (sx[m]*sw[n]), +bias, relu, store bf16
#pragma unroll
    for (int mt = 0; mt < 4; mt++) {
        const int m = m0 + wm + mt * 16 + (lane >> 2);
        const float sxm0 = sx[m], sxm1 = sx[m + 8];
#pragma unroll
        for (int nt = 0; nt < 4; nt++) {
            const int n = n0 + wn + nt * 8 + 2 * (lane & 3);
            const float2 bv  = *(const float2*)&bias[n];
            const float2 swv = *(const float2*)&sw[n];
            float c0 = fmaxf(fmaf((float)acc[mt][nt][0], sxm0 * swv.x, bv.x), 0.0f);
            float c1 = fmaxf(fmaf((float)acc[mt][nt][1], sxm0 * swv.y, bv.y), 0.0f);
            float c2 = fmaxf(fmaf((float)acc[mt][nt][2], sxm1 * swv.x, bv.x), 0.0f);
            float c3 = fmaxf(fmaf((float)acc[mt][nt][3], sxm1 * swv.y, bv.y), 0.0f);
            *(__nv_bfloat162*)(Zb + (size_t)m * HID + n)       = __floats2bfloat162_rn(c0, c1);
            *(__nv_bfloat162*)(Zb + (size_t)(m + 8) * HID + n) = __floats2bfloat162_rn(c2, c3);
        }
    }
}

// ============================================================================
// Candidate select: per token, threshold T = RANK-th largest bf16 key via
// 2-level (8+8 bit) histogram; collect all indices with key >= T.
// Row cached in smem: 1 global pass instead of 3 (full-row uint4 indexing).
// ============================================================================
#define SEL_SMEM (HID * 2)   // 57344 B

__global__ void select_kernel(const __nv_bfloat16* __restrict__ Zb,
                              int* __restrict__ cand_idx, int* __restrict__ cand_cnt)
{
    extern __shared__ unsigned srow[];            // HID/2 uints
    __shared__ unsigned hist[256];
    __shared__ unsigned hist2[256];
    __shared__ int s_bstar; __shared__ unsigned s_chi;
    __shared__ unsigned s_T;
    __shared__ unsigned s_pos;

    const int n = blockIdx.x, tid = threadIdx.x, lane = tid & 31;
    const uint4* row4 = (const uint4*)(Zb + (size_t)n * HID);   // 8 keys per uint4

    for (int i = tid; i < 256; i += 256) { hist[i] = 0; hist2[i] = 0; }
    if (tid == 0) s_pos = 0;
    __syncthreads();

    // pass 1 (global, fused smem fill): high-byte histogram
#pragma unroll 2
    for (int u = 0; u < 14; u++) {
        int q = tid + u * 256;
        uint4 v = row4[q];
        ((uint4*)srow)[q] = v;
        unsigned w[4] = {v.x, v.y, v.z, v.w};
#pragma unroll
        for (int j = 0; j < 4; j++) {
#pragma unroll
            for (int t = 0; t < 2; t++) {
                int bin = (int)((t ? (w[j] >> 16) : (w[j] & 0xffffu)) >> 8);
                unsigned mask = __match_any_sync(0xffffffffu, bin);
                if (lane == __ffs(mask) - 1) atomicAdd(&hist[bin], __popc(mask));
            }
        }
    }
    __syncthreads();

    if (tid < 32) {   // find b*, C_hi (count strictly above b*)
        const int base = 248 - 8 * lane;   // lane 0 covers top bins
        unsigned loc = 0;
#pragma unroll
        for (int j = 0; j < 8; j++) loc += hist[base + j];
        unsigned pref = loc;
        for (int o = 1; o < 32; o <<= 1) {
            unsigned t = __shfl_up_sync(0xffffffffu, pref, o);
            if (lane >= o) pref += t;
        }
        unsigned bal = __ballot_sync(0xffffffffu, pref >= RANK);
        int fl = __ffs(bal) - 1;
        if (lane == fl) {
            unsigned acc = pref - loc;
            for (int b = 255 - 8 * fl; b >= 248 - 8 * fl; b--) {
                unsigned c = hist[b];
                if (acc + c >= RANK) { s_bstar = b; s_chi = acc; break; }
                acc += c;
            }
        }
    }
    __syncthreads();
    const int bstar = s_bstar;
    const unsigned chi = s_chi;

    // pass 2 (smem): low-byte histogram within boundary bin
#pragma unroll 2
    for (int u = 0; u < 14; u++) {
        int q = tid + u * 256;
        uint4 v = ((const uint4*)srow)[q];
        unsigned w[4] = {v.x, v.y, v.z, v.w};
#pragma unroll
        for (int j = 0; j < 4; j++) {
#pragma unroll
            for (int t = 0; t < 2; t++) {
                unsigned key = t ? (w[j] >> 16) : (w[j] & 0xffffu);
                int in = ((int)(key >> 8) == bstar);
                unsigned act = __ballot_sync(0xffffffffu, in);
                if (in) {
                    int low = (int)(key & 0xff);
                    unsigned mask = __match_any_sync(act, low);
                    if (lane == __ffs(mask) - 1) atomicAdd(&hist2[low], __popc(mask));
                }
            }
        }
    }
    __syncthreads();

    if (tid < 32) {
        const int base = 248 - 8 * lane;
        unsigned loc = 0;
#pragma unroll
        for (int j = 0; j < 8; j++) loc += hist2[base + j];
        unsigned pref = loc;
        for (int o = 1; o < 32; o <<= 1) {
            unsigned t = __shfl_up_sync(0xffffffffu, pref, o);
            if (lane >= o) pref += t;
        }
        const unsigned need = RANK - chi;   // >= 1
        unsigned bal = __ballot_sync(0xffffffffu, pref >= need);
        int fl = __ffs(bal) - 1;
        if (lane == fl) {
            unsigned acc = pref - loc;
            for (int b = 255 - 8 * fl; b >= 248 - 8 * fl; b--) {
                unsigned c = hist2[b];
                if (acc + c >= need) { s_T = ((unsigned)bstar << 8) | (unsigned)b; break; }
                acc += c;
            }
        }
    }
    __syncthreads();
    const unsigned T = s_T;

    // pass 3 (smem): collect indices with key >= T
#pragma unroll 2
    for (int u = 0; u < 14; u++) {
        int q = tid + u * 256;
        uint4 v = ((const uint4*)srow)[q];
        unsigned w[4] = {v.x, v.y, v.z, v.w};
#pragma unroll
        for (int j = 0; j < 4; j++) {
            int idx0 = q * 8 + j * 2;
            unsigned k0 = w[j] & 0xffffu, k1 = w[j] >> 16;
            if (k0 >= T) { unsigned p = atomicAdd(&s_pos, 1u); if (p < CAP) cand_idx[(size_t)n * CAP + p] = idx0; }
            if (k1 >= T) { unsigned p = atomicAdd(&s_pos, 1u); if (p < CAP) cand_idx[(size_t)n * CAP + p] = idx0 + 1; }
        }
    }
    __syncthreads();
    if (tid == 0) cand_cnt[n] = (int)min(s_pos, (unsigned)CAP);
}

// ============================================================================
// Exact refine: recompute candidate dots in fp32, take exact top-32,
// write z_sparse (zero + scatter), tki/tkv, sparsity partials.
// ============================================================================
__global__ __launch_bounds__(256)
void refine_kernel(const float* __restrict__ x, const float* __restrict__ W,
                   const float* __restrict__ be,
                   const int* __restrict__ cand_idx, const int* __restrict__ cand_cnt,
                   float* __restrict__ z_sparse,
                   int* __restrict__ tki, float* __restrict__ tkv,
                   float* __restrict__ sp_partial)
{
    __shared__ float sx[DIM];
    __shared__ float cval[CAP];
    __shared__ int   cidx[CAP];
    __shared__ float selv[TOPK];
    __shared__ int   seli[TOPK];

    const int n = blockIdx.x, tid = threadIdx.x, lane = tid & 31, wid = tid >> 5;
    const int M = cand_cnt[n];

    for (int i = tid; i < DIM / 4; i += 256)
        ((float4*)sx)[i] = ((const float4*)(x + (size_t)n * DIM))[i];
    for (int i = tid; i < CAP; i += 256) { cval[i] = -1e30f; cidx[i] = 0x7fffffff; }
    __syncthreads();

    for (int c = wid; c < M; c += 8) {
        const int h = cand_idx[(size_t)n * CAP + c];
        const float4* wr = (const float4*)(W + (size_t)h * DIM);
        float s = 0.0f;
#pragma unroll
        for (int j = 0; j < 28; j++) {
            float4 wv = wr[lane + 32 * j];
            float4 xv = ((const float4*)sx)[lane + 32 * j];
            s = fmaf(wv.x, xv.x, fmaf(wv.y, xv.y, fmaf(wv.z, xv.z, fmaf(wv.w, xv.w, s))));
        }
#pragma unroll
        for (int o = 16; o; o >>= 1) s += __shfl_down_sync(0xffffffffu, s, o);
        if (lane == 0) {
            float v = s + be[h];
            cval[c] = v > 0.0f ? v : 0.0f;
            cidx[c] = h;
        }
    }
    __syncthreads();

    // warp 0: exact top-32 over CAP slots (value desc, index asc tie-break)
    if (wid == 0) {
        float v[3]; int id[3];
#pragma unroll
        for (int t = 0; t < 3; t++) { v[t] = cval[lane + 32 * t]; id[t] = cidx[lane + 32 * t]; }
        for (int it = 0; it < TOPK; it++) {
            float bv = v[0]; int bi = id[0]; int bs = 0;
#pragma unroll
            for (int t = 1; t < 3; t++)
                if (v[t] > bv || (v[t] == bv && id[t] < bi)) { bv = v[t]; bi = id[t]; bs = t; }
            float rv = bv; int ri = bi, rl = lane, rs = bs;
#pragma unroll
            for (int o = 16; o; o >>= 1) {
                float ov = __shfl_down_sync(0xffffffffu, rv, o);
                int   oi = __shfl_down_sync(0xffffffffu, ri, o);
                int   ol = __shfl_down_sync(0xffffffffu, rl, o);
                int   os = __shfl_down_sync(0xffffffffu, rs, o);
                if (ov > rv || (ov == rv && oi < ri)) { rv = ov; ri = oi; rl = ol; rs = os; }
            }
            rv = __shfl_sync(0xffffffffu, rv, 0);
            ri = __shfl_sync(0xffffffffu, ri, 0);
            rl = __shfl_sync(0xffffffffu, rl, 0);
            rs = __shfl_sync(0xffffffffu, rs, 0);
            if (lane == 0) { selv[it] = rv; seli[it] = ri; }
            if (lane == rl) v[rs] = -1e30f;
        }
    }
    __syncthreads();

    float* orow = z_sparse + (size_t)n * HID;
    for (int i = tid; i < HID / 4; i += 256)
        ((float4*)orow)[i] = make_float4(0.f, 0.f, 0.f, 0.f);
    __syncthreads();
    if (tid < TOPK) {
        orow[seli[tid]] = selv[tid];
        tki[n * TOPK + tid] = seli[tid];
        tkv[n * TOPK + tid] = selv[tid];
    }
    if (tid == 0) {
        float s = 0.0f;
#pragma unroll
        for (int i = 0; i < TOPK; i++) s += selv[i];
        sp_partial[n] = s;
    }
}

// ---------------- W_dec transpose: [DIM, HID] -> [HID, DIM] ----------------
__global__ void transpose_kernel(const float* __restrict__ Wd, float* __restrict__ WdT)
{
    __shared__ float tile[32][33];
    int h0 = blockIdx.x * 32;
    int d0 = blockIdx.y * 32;
    int x = threadIdx.x, y = threadIdx.y;
#pragma unroll
    for (int j = 0; j < 32; j += 8)
        tile[y + j][x] = Wd[(size_t)(d0 + y + j) * HID + h0 + x];
    __syncthreads();
#pragma unroll
    for (int j = 0; j < 32; j += 8)
        WdT[(size_t)(h0 + y + j) * DIM + d0 + x] = tile[x][y + j];
}

// ---------------- sparse decode + recon partials ----------------
__global__ void decode_kernel(const float* __restrict__ WdT,
                              const float* __restrict__ x,
                              const float* __restrict__ b_dec,
                              const int* __restrict__ tki,
                              const float* __restrict__ tkv,
                              float* __restrict__ xhat_out,
                              float* __restrict__ recon_partial)
{
    const int n = blockIdx.x, tid = threadIdx.x;
    __shared__ float vals[TOPK];
    __shared__ int   idxs[TOPK];
    __shared__ float wred[16];

    if (tid < TOPK) { vals[tid] = tkv[n * TOPK + tid]; idxs[tid] = tki[n * TOPK + tid]; }
    __syncthreads();

    float acc[7];
#pragma unroll
    for (int i = 0; i < 7; i++) acc[i] = 0.0f;
    for (int k = 0; k < TOPK; k++) {
        const float* wrow = WdT + (size_t)idxs[k] * DIM;
        float v = vals[k];
#pragma unroll
        for (int i = 0; i < 7; i++) acc[i] = fmaf(v, wrow[tid + i * 512], acc[i]);
    }
    float ls = 0.0f;
#pragma unroll
    for (int i = 0; i < 7; i++) {
        int d = tid + i * 512;
        float xh = acc[i] + b_dec[d];
        xhat_out[(size_t)n * DIM + d] = xh;
        float df = xh - x[(size_t)n * DIM + d];
        ls = fmaf(df, df, ls);
    }
#pragma unroll
    for (int o = 16; o; o >>= 1) ls += __shfl_down_sync(0xffffffffu, ls, o);
    if ((tid & 31) == 0) wred[tid >> 5] = ls;
    __syncthreads();
    if (tid < 32) {
        float v = (tid < 16) ? wred[tid] : 0.0f;
#pragma unroll
        for (int o = 8; o; o >>= 1) v += __shfl_down_sync(0xffffffffu, v, o);
        if (tid == 0) recon_partial[n] = v;
    }
}

// ---------------- final scalar reduction ----------------
__global__ void finalize_kernel(const float* __restrict__ recon_partial,
                                const float* __restrict__ sp_partial,
                                float* __restrict__ out_recon,
                                float* __restrict__ out_sp)
{
    __shared__ float s1[1024], s2[1024];
    const int tid = threadIdx.x;
    float a = 0.0f, b = 0.0f;
    for (int i = tid; i < N_TOK; i += 1024) { a += recon_partial[i]; b += sp_partial[i]; }
    s1[tid] = a; s2[tid] = b;
    __syncthreads();
    for (int s = 512; s > 0; s >>= 1) {
        if (tid < s) { s1[tid] += s1[tid + s]; s2[tid] += s2[tid + s]; }
        __syncthreads();
    }
    if (tid == 0) {
        out_recon[0] = s1[0] / ((float)N_TOK * (float)DIM);
        out_sp[0]    = s2[0] / ((float)N_TOK * (float)HID);
    }
}

// ---------------- launch ----------------
extern "C" void kernel_launch(void* const* d_in, const int* in_sizes, int n_in,
                              void* d_out, int out_size)
{
    const float* x     = (const float*)d_in[0];   // [N_TOK, DIM]
    const float* W_enc = (const float*)d_in[1];   // [HID, DIM]
    const float* b_enc = (const float*)d_in[2];   // [HID]
    const float* W_dec = (const float*)d_in[3];   // [DIM, HID]
    const float* b_dec = (const float*)d_in[4];   // [DIM]

    float* out = (float*)d_out;
    const size_t OFF_XHAT  = 0;
    const size_t OFF_Z     = (size_t)N_TOK * DIM;
    const size_t OFF_RECON = OFF_Z + (size_t)N_TOK * HID;
    const size_t OFF_SP    = OFF_RECON + 1;

    cudaFuncSetAttribute(encode_mma_kernel, cudaFuncAttributeMaxDynamicSharedMemorySize,
                         GEMM_SMEM);
    cudaFuncSetAttribute(select_kernel, cudaFuncAttributeMaxDynamicSharedMemorySize,
                         SEL_SMEM);

    int8_t* x8 = nullptr; cudaGetSymbolAddress((void**)&x8, g_x8);
    int8_t* w8 = nullptr; cudaGetSymbolAddress((void**)&w8, g_w8);
    float* sxp = nullptr; cudaGetSymbolAddress((void**)&sxp, g_sx);
    float* swp = nullptr; cudaGetSymbolAddress((void**)&swp, g_sw);
    __nv_bfloat16* Zb = nullptr; cudaGetSymbolAddress((void**)&Zb, g_Zb);
    float* WdT = nullptr; cudaGetSymbolAddress((void**)&WdT, g_WdT);
    int*   cdi = nullptr; cudaGetSymbolAddress((void**)&cdi, g_cand);
    int*   cdc = nullptr; cudaGetSymbolAddress((void**)&cdc, g_ccnt);
    int*   tki = nullptr; cudaGetSymbolAddress((void**)&tki, g_tki);
    float* tkv = nullptr; cudaGetSymbolAddress((void**)&tkv, g_tkv);
    float* rp  = nullptr; cudaGetSymbolAddress((void**)&rp,  g_rp);
    float* sp  = nullptr; cudaGetSymbolAddress((void**)&sp,  g_sp);

    // 1) per-row int8 quantization of x and W_enc
    quant_rows_kernel<<<N_TOK, 256>>>(x, x8, sxp, DIM);
    quant_rows_kernel<<<HID, 256>>>(W_enc, w8, swp, DIM);

    // 2) transpose W_dec (independent)
    transpose_kernel<<<dim3(HID / 32, DIM / 32), dim3(32, 8)>>>(W_dec, WdT);

    // 3) encoder GEMM on int8 tensor cores (approx), relu'd bf16 z
    encode_mma_kernel<<<(N_TOK / 128) * (HID / 128), 256, GEMM_SMEM>>>(
        x8, w8, sxp, swp, b_enc, Zb);

    // 4) candidate select (top-RANK superset per token)
    select_kernel<<<N_TOK, 256, SEL_SMEM>>>(Zb, cdi, cdc);

    // 5) exact fp32 refine -> z_sparse, top-32 lists, sparsity partials
    refine_kernel<<<N_TOK, 256>>>(x, W_enc, b_enc, cdi, cdc, out + OFF_Z, tki, tkv, sp);

    // 6) sparse decode -> x_hat + recon partials
    decode_kernel<<<N_TOK, 512>>>(WdT, x, b_dec, tki, tkv, out + OFF_XHAT, rp);

    // 7) scalar losses
    finalize_kernel<<<1, 1024>>>(rp, sp, out + OFF_RECON, out + OFF_SP);
}

// round 15
// speedup vs baseline: 1.9548x; 1.9548x over previous
#include <cuda_runtime.h>
#include <cuda_bf16.h>
#include <cstdint>
#include <cstddef>

// Problem constants
#define N_TOK 4096
#define DIM   3584
#define HID   28672
#define TOPK  32
#define RANK  40      // candidate rank target (margin 8 ranks ~ 13 sigma for bf16 encode)
#define CAP   96      // candidate capacity per token

#define M_HALF (N_TOK / 2)   // 2048 tokens per encode/select/refine/decode chunk

// ---------------- scratch (device globals) ----------------
__device__ __nv_bfloat16 g_xb[(size_t)N_TOK * DIM];   // x in bf16
__device__ __nv_bfloat16 g_wb[(size_t)HID * DIM];     // W_enc in bf16
__device__ __nv_bfloat16 g_Zb[(size_t)N_TOK * HID];   // approx z (relu'd) in bf16
__device__ float g_WdT[(size_t)HID * DIM];            // W_dec transposed [H, D]
__device__ int   g_cand[(size_t)N_TOK * CAP];
__device__ int   g_ccnt[N_TOK];
__device__ int   g_tki[N_TOK * TOPK];
__device__ float g_tkv[N_TOK * TOPK];
__device__ float g_rp[N_TOK];
__device__ float g_sp[N_TOK];

// ---------------- small PTX helpers (all baseline sm_80+ features) ----------------
__device__ __forceinline__ uint32_t smem_u32(const void* p) {
    uint32_t a;
    asm("{ .reg .u64 t; cvta.to.shared.u64 t, %1; cvt.u32.u64 %0, t; }" : "=r"(a) : "l"(p));
    return a;
}
__device__ __forceinline__ void cp_async16(uint32_t smaddr, const void* g) {
    asm volatile("cp.async.cg.shared.global [%0], [%1], 16;" :: "r"(smaddr), "l"(g) : "memory");
}
__device__ __forceinline__ void cp_commit() {
    asm volatile("cp.async.commit_group;" ::: "memory");
}
__device__ __forceinline__ void cp_wait2() {
    asm volatile("cp.async.wait_group 2;" ::: "memory");
}
__device__ __forceinline__ void ldsm4(uint32_t* r, uint32_t addr) {
    asm volatile("ldmatrix.sync.aligned.m8n8.x4.shared.b16 {%0,%1,%2,%3}, [%4];"
                 : "=r"(r[0]), "=r"(r[1]), "=r"(r[2]), "=r"(r[3]) : "r"(addr));
}
__device__ __forceinline__ void mma16816(float* c, const uint32_t* a, uint32_t b0, uint32_t b1) {
    asm volatile("mma.sync.aligned.m16n8k16.row.col.f32.bf16.bf16.f32 "
                 "{%0,%1,%2,%3},{%4,%5,%6,%7},{%8,%9},{%0,%1,%2,%3};"
                 : "+f"(c[0]), "+f"(c[1]), "+f"(c[2]), "+f"(c[3])
                 : "r"(a[0]), "r"(a[1]), "r"(a[2]), "r"(a[3]), "r"(b0), "r"(b1));
}

// ---------------- fp32 -> bf16 conversion ----------------
__global__ void to_bf16_kernel(const float* __restrict__ src, __nv_bfloat16* __restrict__ dst,
                               size_t n4)
{
    size_t i = (size_t)blockIdx.x * blockDim.x + threadIdx.x;
    if (i < n4) {
        float4 v = ((const float4*)src)[i];
        __nv_bfloat162 lo = __floats2bfloat162_rn(v.x, v.y);
        __nv_bfloat162 hi = __floats2bfloat162_rn(v.z, v.w);
        ((__nv_bfloat162*)dst)[2 * i]     = lo;
        ((__nv_bfloat162*)dst)[2 * i + 1] = hi;
    }
}

// ============================================================================
// Encode GEMM (bf16, mma.sync m16n8k16): Zb = relu(x @ W_enc^T + b_enc) as bf16
// R6-proven config; chunked over M (m_base param) for cross-stream pipelining.
// Per launch: 2048 tokens -> 16 M-tiles x 224 N-tiles = 3584 CTAs.
// Panel remap: 128 CTAs/panel = 16 M x 8 N.
// ============================================================================
#define GM_BK      32
#define GM_STAGES  4
#define ROW_BYTES  80                    // 64B data + 16B pad
#define STAGE_B    (128 * ROW_BYTES)     // per-matrix stage: 10240 B
#define GEMM_SMEM  (GM_STAGES * 2 * STAGE_B)   // 81920 B

__global__ __launch_bounds__(256, 2)
void encode_mma_kernel(const __nv_bfloat16* __restrict__ Abf,   // [N_TOK][DIM]
                       const __nv_bfloat16* __restrict__ Bbf,   // [HID][DIM]
                       const float* __restrict__ bias,
                       __nv_bfloat16* __restrict__ Zb,          // [N_TOK][HID]
                       int m_base)
{
    extern __shared__ char sm[];
    const uint32_t smb = smem_u32(sm);
    const int tid = threadIdx.x, lane = tid & 31, wid = tid >> 5;

    const int L = blockIdx.x;
    const int panel = L >> 7, within = L & 127;
    const int m0 = m_base + (within & 15) * 128;
    const int n0 = (panel * 8 + (within >> 4)) * 128;

    const int wm = (wid >> 2) * 64;      // warp M offset (0/64)
    const int wn = (wid & 3) * 32;       // warp N offset (0..96)

    auto load_stage = [&](int it, int s) {
        const uint32_t sa = smb + (uint32_t)s * (2 * STAGE_B);
        const uint32_t sb = sa + STAGE_B;
#pragma unroll
        for (int u = 0; u < 2; u++) {
            int g = tid + u * 256;
            int row = g >> 2, ch = g & 3;
            cp_async16(sa + row * ROW_BYTES + ch * 16,
                       Abf + (size_t)(m0 + row) * DIM + it * GM_BK + ch * 8);
            cp_async16(sb + row * ROW_BYTES + ch * 16,
                       Bbf + (size_t)(n0 + row) * DIM + it * GM_BK + ch * 8);
        }
    };

    const int NIT = DIM / GM_BK;   // 112
    for (int s = 0; s < 3; s++) { load_stage(s, s); cp_commit(); }

    float acc[4][4][4];
#pragma unroll
    for (int i = 0; i < 4; i++)
#pragma unroll
        for (int j = 0; j < 4; j++)
#pragma unroll
            for (int k = 0; k < 4; k++) acc[i][j][k] = 0.0f;

    const int a_row  = wm + (lane & 15);
    const int a_kb   = (lane >> 4) * 16;
    const int b_row  = wn + ((lane >> 4) & 1) * 8 + (lane & 7);
    const int b_kb   = ((lane >> 3) & 1) * 16;

    for (int i = 0; i < NIT; i++) {
        cp_wait2();
        __syncthreads();
        const int s = i & 3;
        const uint32_t sa = smb + (uint32_t)s * (2 * STAGE_B);
        const uint32_t sb = sa + STAGE_B;

        uint32_t a[4][4], b[2][4];
        // ---- k-half 0 ----
#pragma unroll
        for (int mt = 0; mt < 4; mt++)
            ldsm4(a[mt], sa + (a_row + mt * 16) * ROW_BYTES + a_kb);
#pragma unroll
        for (int p = 0; p < 2; p++)
            ldsm4(b[p], sb + (b_row + p * 16) * ROW_BYTES + b_kb);

        if (i + 3 < NIT) load_stage(i + 3, (i + 3) & 3);
        cp_commit();

#pragma unroll
        for (int mt = 0; mt < 4; mt++)
#pragma unroll
            for (int nt = 0; nt < 4; nt++)
                mma16816(acc[mt][nt], a[mt],
                         b[nt >> 1][(nt & 1) * 2], b[nt >> 1][(nt & 1) * 2 + 1]);

        // ---- k-half 1 ----
#pragma unroll
        for (int mt = 0; mt < 4; mt++)
            ldsm4(a[mt], sa + (a_row + mt * 16) * ROW_BYTES + 32 + a_kb);
#pragma unroll
        for (int p = 0; p < 2; p++)
            ldsm4(b[p], sb + (b_row + p * 16) * ROW_BYTES + 32 + b_kb);

#pragma unroll
        for (int mt = 0; mt < 4; mt++)
#pragma unroll
            for (int nt = 0; nt < 4; nt++)
                mma16816(acc[mt][nt], a[mt],
                         b[nt >> 1][(nt & 1) * 2], b[nt >> 1][(nt & 1) * 2 + 1]);
    }

    // epilogue: +bias, relu, store bf16
#pragma unroll
    for (int mt = 0; mt < 4; mt++) {
#pragma unroll
        for (int nt = 0; nt < 4; nt++) {
            const int m = m0 + wm + mt * 16 + (lane >> 2);
            const int n = n0 + wn + nt * 8 + 2 * (lane & 3);
            const float2 bv = *(const float2*)&bias[n];
            float c0 = fmaxf(acc[mt][nt][0] + bv.x, 0.0f);
            float c1 = fmaxf(acc[mt][nt][1] + bv.y, 0.0f);
            float c2 = fmaxf(acc[mt][nt][2] + bv.x, 0.0f);
            float c3 = fmaxf(acc[mt][nt][3] + bv.y, 0.0f);
            *(__nv_bfloat162*)(Zb + (size_t)m * HID + n)       = __floats2bfloat162_rn(c0, c1);
            *(__nv_bfloat162*)(Zb + (size_t)(m + 8) * HID + n) = __floats2bfloat162_rn(c2, c3);
        }
    }
}

// ============================================================================
// Candidate select (tok_base chunk): threshold T = RANK-th largest bf16 key via
// 2-level histogram on the smem-cached row; collect indices with key >= T.
// ============================================================================
#define SEL_SMEM (HID * 2)   // 57344 B

__global__ void select_kernel(const __nv_bfloat16* __restrict__ Zb,
                              int* __restrict__ cand_idx, int* __restrict__ cand_cnt,
                              int tok_base)
{
    extern __shared__ unsigned srow[];            // HID/2 uints
    __shared__ unsigned hist[256];
    __shared__ unsigned hist2[256];
    __shared__ int s_bstar; __shared__ unsigned s_chi;
    __shared__ unsigned s_T;
    __shared__ unsigned s_pos;

    const int n = tok_base + blockIdx.x, tid = threadIdx.x, lane = tid & 31;
    const uint4* row4 = (const uint4*)(Zb + (size_t)n * HID);   // 8 keys per uint4

    for (int i = tid; i < 256; i += 256) { hist[i] = 0; hist2[i] = 0; }
    if (tid == 0) s_pos = 0;
    __syncthreads();

    // pass 1 (global, fused smem fill): high-byte histogram
#pragma unroll 2
    for (int u = 0; u < 14; u++) {
        int q = tid + u * 256;
        uint4 v = row4[q];
        ((uint4*)srow)[q] = v;
        unsigned w[4] = {v.x, v.y, v.z, v.w};
#pragma unroll
        for (int j = 0; j < 4; j++) {
#pragma unroll
            for (int t = 0; t < 2; t++) {
                int bin = (int)((t ? (w[j] >> 16) : (w[j] & 0xffffu)) >> 8);
                unsigned mask = __match_any_sync(0xffffffffu, bin);
                if (lane == __ffs(mask) - 1) atomicAdd(&hist[bin], __popc(mask));
            }
        }
    }
    __syncthreads();

    if (tid < 32) {   // find b*, C_hi (count strictly above b*)
        const int base = 248 - 8 * lane;
        unsigned loc = 0;
#pragma unroll
        for (int j = 0; j < 8; j++) loc += hist[base + j];
        unsigned pref = loc;
        for (int o = 1; o < 32; o <<= 1) {
            unsigned t = __shfl_up_sync(0xffffffffu, pref, o);
            if (lane >= o) pref += t;
        }
        unsigned bal = __ballot_sync(0xffffffffu, pref >= RANK);
        int fl = __ffs(bal) - 1;
        if (lane == fl) {
            unsigned acc = pref - loc;
            for (int b = 255 - 8 * fl; b >= 248 - 8 * fl; b--) {
                unsigned c = hist[b];
                if (acc + c >= RANK) { s_bstar = b; s_chi = acc; break; }
                acc += c;
            }
        }
    }
    __syncthreads();
    const int bstar = s_bstar;
    const unsigned chi = s_chi;

    // pass 2 (smem): low-byte histogram within boundary bin
#pragma unroll 2
    for (int u = 0; u < 14; u++) {
        int q = tid + u * 256;
        uint4 v = ((const uint4*)srow)[q];
        unsigned w[4] = {v.x, v.y, v.z, v.w};
#pragma unroll
        for (int j = 0; j < 4; j++) {
#pragma unroll
            for (int t = 0; t < 2; t++) {
                unsigned key = t ? (w[j] >> 16) : (w[j] & 0xffffu);
                int in = ((int)(key >> 8) == bstar);
                unsigned act = __ballot_sync(0xffffffffu, in);
                if (in) {
                    int low = (int)(key & 0xff);
                    unsigned mask = __match_any_sync(act, low);
                    if (lane == __ffs(mask) - 1) atomicAdd(&hist2[low], __popc(mask));
                }
            }
        }
    }
    __syncthreads();

    if (tid < 32) {
        const int base = 248 - 8 * lane;
        unsigned loc = 0;
#pragma unroll
        for (int j = 0; j < 8; j++) loc += hist2[base + j];
        unsigned pref = loc;
        for (int o = 1; o < 32; o <<= 1) {
            unsigned t = __shfl_up_sync(0xffffffffu, pref, o);
            if (lane >= o) pref += t;
        }
        const unsigned need = RANK - chi;   // >= 1
        unsigned bal = __ballot_sync(0xffffffffu, pref >= need);
        int fl = __ffs(bal) - 1;
        if (lane == fl) {
            unsigned acc = pref - loc;
            for (int b = 255 - 8 * fl; b >= 248 - 8 * fl; b--) {
                unsigned c = hist2[b];
                if (acc + c >= need) { s_T = ((unsigned)bstar << 8) | (unsigned)b; break; }
                acc += c;
            }
        }
    }
    __syncthreads();
    const unsigned T = s_T;

    // pass 3 (smem): collect indices with key >= T
#pragma unroll 2
    for (int u = 0; u < 14; u++) {
        int q = tid + u * 256;
        uint4 v = ((const uint4*)srow)[q];
        unsigned w[4] = {v.x, v.y, v.z, v.w};
#pragma unroll
        for (int j = 0; j < 4; j++) {
            int idx0 = q * 8 + j * 2;
            unsigned k0 = w[j] & 0xffffu, k1 = w[j] >> 16;
            if (k0 >= T) { unsigned p = atomicAdd(&s_pos, 1u); if (p < CAP) cand_idx[(size_t)n * CAP + p] = idx0; }
            if (k1 >= T) { unsigned p = atomicAdd(&s_pos, 1u); if (p < CAP) cand_idx[(size_t)n * CAP + p] = idx0 + 1; }
        }
    }
    __syncthreads();
    if (tid == 0) cand_cnt[n] = (int)min(s_pos, (unsigned)CAP);
}

// ============================================================================
// Exact refine (tok_base chunk): fp32 candidate dots, exact top-32,
// z_sparse scatter, tki/tkv, sparsity partials.
// ============================================================================
__global__ __launch_bounds__(256)
void refine_kernel(const float* __restrict__ x, const float* __restrict__ W,
                   const float* __restrict__ be,
                   const int* __restrict__ cand_idx, const int* __restrict__ cand_cnt,
                   float* __restrict__ z_sparse,
                   int* __restrict__ tki, float* __restrict__ tkv,
                   float* __restrict__ sp_partial, int tok_base)
{
    __shared__ float sx[DIM];
    __shared__ float cval[CAP];
    __shared__ int   cidx[CAP];
    __shared__ float selv[TOPK];
    __shared__ int   seli[TOPK];

    const int n = tok_base + blockIdx.x, tid = threadIdx.x, lane = tid & 31, wid = tid >> 5;
    const int M = cand_cnt[n];

    for (int i = tid; i < DIM / 4; i += 256)
        ((float4*)sx)[i] = ((const float4*)(x + (size_t)n * DIM))[i];
    for (int i = tid; i < CAP; i += 256) { cval[i] = -1e30f; cidx[i] = 0x7fffffff; }
    __syncthreads();

    for (int c = wid; c < M; c += 8) {
        const int h = cand_idx[(size_t)n * CAP + c];
        const float4* wr = (const float4*)(W + (size_t)h * DIM);
        float s = 0.0f;
#pragma unroll
        for (int j = 0; j < 28; j++) {
            float4 wv = wr[lane + 32 * j];
            float4 xv = ((const float4*)sx)[lane + 32 * j];
            s = fmaf(wv.x, xv.x, fmaf(wv.y, xv.y, fmaf(wv.z, xv.z, fmaf(wv.w, xv.w, s))));
        }
#pragma unroll
        for (int o = 16; o; o >>= 1) s += __shfl_down_sync(0xffffffffu, s, o);
        if (lane == 0) {
            float v = s + be[h];
            cval[c] = v > 0.0f ? v : 0.0f;
            cidx[c] = h;
        }
    }
    __syncthreads();

    if (wid == 0) {
        float v[3]; int id[3];
#pragma unroll
        for (int t = 0; t < 3; t++) { v[t] = cval[lane + 32 * t]; id[t] = cidx[lane + 32 * t]; }
        for (int it = 0; it < TOPK; it++) {
            float bv = v[0]; int bi = id[0]; int bs = 0;
#pragma unroll
            for (int t = 1; t < 3; t++)
                if (v[t] > bv || (v[t] == bv && id[t] < bi)) { bv = v[t]; bi = id[t]; bs = t; }
            float rv = bv; int ri = bi, rl = lane, rs = bs;
#pragma unroll
            for (int o = 16; o; o >>= 1) {
                float ov = __shfl_down_sync(0xffffffffu, rv, o);
                int   oi = __shfl_down_sync(0xffffffffu, ri, o);
                int   ol = __shfl_down_sync(0xffffffffu, rl, o);
                int   os = __shfl_down_sync(0xffffffffu, rs, o);
                if (ov > rv || (ov == rv && oi < ri)) { rv = ov; ri = oi; rl = ol; rs = os; }
            }
            rv = __shfl_sync(0xffffffffu, rv, 0);
            ri = __shfl_sync(0xffffffffu, ri, 0);
            rl = __shfl_sync(0xffffffffu, rl, 0);
            rs = __shfl_sync(0xffffffffu, rs, 0);
            if (lane == 0) { selv[it] = rv; seli[it] = ri; }
            if (lane == rl) v[rs] = -1e30f;
        }
    }
    __syncthreads();

    float* orow = z_sparse + (size_t)n * HID;
    for (int i = tid; i < HID / 4; i += 256)
        ((float4*)orow)[i] = make_float4(0.f, 0.f, 0.f, 0.f);
    __syncthreads();
    if (tid < TOPK) {
        orow[seli[tid]] = selv[tid];
        tki[n * TOPK + tid] = seli[tid];
        tkv[n * TOPK + tid] = selv[tid];
    }
    if (tid == 0) {
        float s = 0.0f;
#pragma unroll
        for (int i = 0; i < TOPK; i++) s += selv[i];
        sp_partial[n] = s;
    }
}

// ---------------- W_dec transpose: [DIM, HID] -> [HID, DIM] ----------------
__global__ void transpose_kernel(const float* __restrict__ Wd, float* __restrict__ WdT)
{
    __shared__ float tile[32][33];
    int h0 = blockIdx.x * 32;
    int d0 = blockIdx.y * 32;
    int x = threadIdx.x, y = threadIdx.y;
#pragma unroll
    for (int j = 0; j < 32; j += 8)
        tile[y + j][x] = Wd[(size_t)(d0 + y + j) * HID + h0 + x];
    __syncthreads();
#pragma unroll
    for (int j = 0; j < 32; j += 8)
        WdT[(size_t)(h0 + y + j) * DIM + d0 + x] = tile[x][y + j];
}

// ---------------- sparse decode + recon partials (tok_base chunk) ----------------
__global__ void decode_kernel(const float* __restrict__ WdT,
                              const float* __restrict__ x,
                              const float* __restrict__ b_dec,
                              const int* __restrict__ tki,
                              const float* __restrict__ tkv,
                              float* __restrict__ xhat_out,
                              float* __restrict__ recon_partial, int tok_base)
{
    const int n = tok_base + blockIdx.x, tid = threadIdx.x;
    __shared__ float vals[TOPK];
    __shared__ int   idxs[TOPK];
    __shared__ float wred[16];

    if (tid < TOPK) { vals[tid] = tkv[n * TOPK + tid]; idxs[tid] = tki[n * TOPK + tid]; }
    __syncthreads();

    float acc[7];
#pragma unroll
    for (int i = 0; i < 7; i++) acc[i] = 0.0f;
    for (int k = 0; k < TOPK; k++) {
        const float* wrow = WdT + (size_t)idxs[k] * DIM;
        float v = vals[k];
#pragma unroll
        for (int i = 0; i < 7; i++) acc[i] = fmaf(v, wrow[tid + i * 512], acc[i]);
    }
    float ls = 0.0f;
#pragma unroll
    for (int i = 0; i < 7; i++) {
        int d = tid + i * 512;
        float xh = acc[i] + b_dec[d];
        xhat_out[(size_t)n * DIM + d] = xh;
        float df = xh - x[(size_t)n * DIM + d];
        ls = fmaf(df, df, ls);
    }
#pragma unroll
    for (int o = 16; o; o >>= 1) ls += __shfl_down_sync(0xffffffffu, ls, o);
    if ((tid & 31) == 0) wred[tid >> 5] = ls;
    __syncthreads();
    if (tid < 32) {
        float v = (tid < 16) ? wred[tid] : 0.0f;
#pragma unroll
        for (int o = 8; o; o >>= 1) v += __shfl_down_sync(0xffffffffu, v, o);
        if (tid == 0) recon_partial[n] = v;
    }
}

// ---------------- final scalar reduction ----------------
__global__ void finalize_kernel(const float* __restrict__ recon_partial,
                                const float* __restrict__ sp_partial,
                                float* __restrict__ out_recon,
                                float* __restrict__ out_sp)
{
    __shared__ float s1[1024], s2[1024];
    const int tid = threadIdx.x;
    float a = 0.0f, b = 0.0f;
    for (int i = tid; i < N_TOK; i += 1024) { a += recon_partial[i]; b += sp_partial[i]; }
    s1[tid] = a; s2[tid] = b;
    __syncthreads();
    for (int s = 512; s > 0; s >>= 1) {
        if (tid < s) { s1[tid] += s1[tid + s]; s2[tid] += s2[tid + s]; }
        __syncthreads();
    }
    if (tid == 0) {
        out_recon[0] = s1[0] / ((float)N_TOK * (float)DIM);
        out_sp[0]    = s2[0] / ((float)N_TOK * (float)HID);
    }
}

// ---------------- launch (multi-stream capture fork/join) ----------------
extern "C" void kernel_launch(void* const* d_in, const int* in_sizes, int n_in,
                              void* d_out, int out_size)
{
    const float* x     = (const float*)d_in[0];   // [N_TOK, DIM]
    const float* W_enc = (const float*)d_in[1];   // [HID, DIM]
    const float* b_enc = (const float*)d_in[2];   // [HID]
    const float* W_dec = (const float*)d_in[3];   // [DIM, HID]
    const float* b_dec = (const float*)d_in[4];   // [DIM]

    float* out = (float*)d_out;
    const size_t OFF_XHAT  = 0;
    const size_t OFF_Z     = (size_t)N_TOK * DIM;
    const size_t OFF_RECON = OFF_Z + (size_t)N_TOK * HID;
    const size_t OFF_SP    = OFF_RECON + 1;

    cudaFuncSetAttribute(encode_mma_kernel, cudaFuncAttributeMaxDynamicSharedMemorySize,
                         GEMM_SMEM);
    cudaFuncSetAttribute(select_kernel, cudaFuncAttributeMaxDynamicSharedMemorySize,
                         SEL_SMEM);

    __nv_bfloat16* xb = nullptr; cudaGetSymbolAddress((void**)&xb, g_xb);
    __nv_bfloat16* wb = nullptr; cudaGetSymbolAddress((void**)&wb, g_wb);
    __nv_bfloat16* Zb = nullptr; cudaGetSymbolAddress((void**)&Zb, g_Zb);
    float* WdT = nullptr; cudaGetSymbolAddress((void**)&WdT, g_WdT);
    int*   cdi = nullptr; cudaGetSymbolAddress((void**)&cdi, g_cand);
    int*   cdc = nullptr; cudaGetSymbolAddress((void**)&cdc, g_ccnt);
    int*   tki = nullptr; cudaGetSymbolAddress((void**)&tki, g_tki);
    float* tkv = nullptr; cudaGetSymbolAddress((void**)&tkv, g_tkv);
    float* rp  = nullptr; cudaGetSymbolAddress((void**)&rp,  g_rp);
    float* sp  = nullptr; cudaGetSymbolAddress((void**)&sp,  g_sp);

    // lazily-created side streams + events (host resources, not device memory)
    static cudaStream_t sW = nullptr, sT = nullptr, sA = nullptr;
    static cudaEvent_t ev0 = nullptr, evW = nullptr, evT = nullptr,
                       evA = nullptr, evAdone = nullptr;
    if (!sW) {
        cudaStreamCreateWithFlags(&sW, cudaStreamNonBlocking);
        cudaStreamCreateWithFlags(&sT, cudaStreamNonBlocking);
        cudaStreamCreateWithFlags(&sA, cudaStreamNonBlocking);
        cudaEventCreateWithFlags(&ev0,    cudaEventDisableTiming);
        cudaEventCreateWithFlags(&evW,    cudaEventDisableTiming);
        cudaEventCreateWithFlags(&evT,    cudaEventDisableTiming);
        cudaEventCreateWithFlags(&evA,    cudaEventDisableTiming);
        cudaEventCreateWithFlags(&evAdone, cudaEventDisableTiming);
    }

    const unsigned ENC_GRID = (M_HALF / 128) * (HID / 128);   // 16 * 224 = 3584

    // fork point
    cudaEventRecord(ev0, 0);

    // side stream sW: W_enc -> bf16
    {
        cudaStreamWaitEvent(sW, ev0, 0);
        size_t nw4 = (size_t)HID * DIM / 4;
        to_bf16_kernel<<<(unsigned)((nw4 + 255) / 256), 256, 0, sW>>>(W_enc, wb, nw4);
        cudaEventRecord(evW, sW);
    }
    // side stream sT: W_dec transpose (needed only by decode)
    {
        cudaStreamWaitEvent(sT, ev0, 0);
        transpose_kernel<<<dim3(HID / 32, DIM / 32), dim3(32, 8), 0, sT>>>(W_dec, WdT);
        cudaEventRecord(evT, sT);
    }

    // main stream: x -> bf16 (overlaps with W conversion)
    {
        size_t nx4 = (size_t)N_TOK * DIM / 4;
        to_bf16_kernel<<<(unsigned)((nx4 + 255) / 256), 256>>>(x, xb, nx4);
    }

    // main: wait for wb, encode chunk A (tokens 0..2047)
    cudaStreamWaitEvent(0, evW, 0);
    encode_mma_kernel<<<ENC_GRID, 256, GEMM_SMEM>>>(xb, wb, b_enc, Zb, 0);
    cudaEventRecord(evA, 0);

    // main: encode chunk B (tokens 2048..4095)
    encode_mma_kernel<<<ENC_GRID, 256, GEMM_SMEM>>>(xb, wb, b_enc, Zb, M_HALF);

    // side stream sA: select/refine/decode for chunk A, overlapping encode B
    {
        cudaStreamWaitEvent(sA, evA, 0);
        select_kernel<<<M_HALF, 256, SEL_SMEM, sA>>>(Zb, cdi, cdc, 0);
        refine_kernel<<<M_HALF, 256, 0, sA>>>(x, W_enc, b_enc, cdi, cdc,
                                              out + OFF_Z, tki, tkv, sp, 0);
        cudaStreamWaitEvent(sA, evT, 0);
        decode_kernel<<<M_HALF, 512, 0, sA>>>(WdT, x, b_dec, tki, tkv,
                                              out + OFF_XHAT, rp, 0);
        cudaEventRecord(evAdone, sA);
    }

    // main: select/refine/decode for chunk B
    select_kernel<<<M_HALF, 256, SEL_SMEM>>>(Zb, cdi, cdc, M_HALF);
    refine_kernel<<<M_HALF, 256>>>(x, W_enc, b_enc, cdi, cdc,
                                   out + OFF_Z, tki, tkv, sp, M_HALF);
    cudaStreamWaitEvent(0, evT, 0);
    decode_kernel<<<M_HALF, 512>>>(WdT, x, b_dec, tki, tkv,
                                   out + OFF_XHAT, rp, M_HALF);

    // join chunk A, then losses
    cudaStreamWaitEvent(0, evAdone, 0);
    finalize_kernel<<<1, 1024>>>(rp, sp, out + OFF_RECON, out + OFF_SP);
}